// round 12
// baseline (speedup 1.0000x reference)
#include <cuda_runtime.h>
#include <cuda_fp16.h>

#define N_NODES 100000
#define N_EDGES 1600000
#define COUT 64
#define CIN 128
#define NBLK_SCAN 391   // ceil(100000/256)

// ---------------- scratch (no allocations allowed) ----------------
__device__ int    g_degi[N_NODES];               // edge in-degree (no self loop)
__device__ float  g_dinv[N_NODES];
__device__ __half g_xsh[(size_t)N_NODES * COUT]; // (x@W)*dinv[row], fp16 payload
__device__ int    g_off[N_NODES];                // CSR offsets (global)
__device__ int    g_cnt[N_NODES];                // cursor: init=off, bin advances
__device__ int    g_srow[N_EDGES];               // CSR-sorted source row ids
__device__ int    g_bsum[512];
__device__ int    g_flag[512];
__device__ float  g_sums[COUT];
__device__ float  g_sumsq[COUT];
__device__ float  g_A[COUT];
__device__ float  g_B[COUT];
// pre-split W, padded to the smem stride (72 halves/row) for uint4 copy
__device__ __half g_whp[128 * 72];
__device__ __half g_wlp[128 * 72];

// ---------------- 1. degree count: 4 edges/thread via int4 ----------------
__global__ void k_deg(const int* __restrict__ col) {
    int t = blockIdx.x * blockDim.x + threadIdx.x;
    if (t < N_EDGES / 4) {
        int4 c = ((const int4*)col)[t];
        atomicAdd(&g_degi[c.x], 1);
        atomicAdd(&g_degi[c.y], 1);
        atomicAdd(&g_degi[c.z], 1);
        atomicAdd(&g_degi[c.w], 1);
    }
}

// ---------------- 2. single-pass scan: dinv + offsets + bin cursor -----------
__global__ void __launch_bounds__(256) k_scan1() {
    __shared__ int s[256];
    __shared__ int r2[256];
    const int tid = threadIdx.x;
    const int bid = blockIdx.x;
    const int i = bid * 256 + tid;
    int v = 0;
    if (i < N_NODES) {
        v = g_degi[i];
        g_dinv[i] = rsqrtf((float)v + 1.0f);   // deg incl self loop
    }
    s[tid] = v;
    __syncthreads();
    #pragma unroll
    for (int d = 1; d < 256; d <<= 1) {
        int t = (tid >= d) ? s[tid - d] : 0;
        __syncthreads();
        s[tid] += t;
        __syncthreads();
    }
    if (tid == 255) {
        atomicExch(&g_bsum[bid], s[255]);
        __threadfence();
        atomicExch(&g_flag[bid], 1);
    }
    int p = 0;
    for (int k = tid; k < bid; k += 256) {
        while (atomicAdd(&g_flag[k], 0) == 0) { }
        p += atomicAdd(&g_bsum[k], 0);
    }
    r2[tid] = p;
    __syncthreads();
    #pragma unroll
    for (int d = 128; d > 0; d >>= 1) {
        if (tid < d) r2[tid] += r2[tid + d];
        __syncthreads();
    }
    if (i < N_NODES) {
        int off = r2[0] + s[tid] - v;
        g_off[i] = off;
        g_cnt[i] = off;          // bin cursor starts at the CSR offset
    }
}

// ---------------- 3. bin: cursor atomic gives absolute position --------------
__global__ void k_bin(const int* __restrict__ rowIdx, const int* __restrict__ colIdx) {
    int t = blockIdx.x * blockDim.x + threadIdx.x;
    if (t < N_EDGES / 4) {
        int4 r = ((const int4*)rowIdx)[t];
        int4 c = ((const int4*)colIdx)[t];
        int p0 = atomicAdd(&g_cnt[c.x], 1);
        int p1 = atomicAdd(&g_cnt[c.y], 1);
        int p2 = atomicAdd(&g_cnt[c.z], 1);
        int p3 = atomicAdd(&g_cnt[c.w], 1);
        g_srow[p0] = r.x;
        g_srow[p1] = r.y;
        g_srow[p2] = r.z;
        g_srow[p3] = r.w;
    }
}

// ---------------- 3b. pre-split W into hi/lo fp16 (padded stride 72) ---------
__device__ __forceinline__ void split16(float v, __half& h, __half& l) {
    h = __float2half_rn(v);
    l = __float2half_rn(v - __half2float(h));
}
__global__ void k_wsplit(const float* __restrict__ W) {
    int idx = blockIdx.x * 256 + threadIdx.x;     // 0..8191
    if (idx < 128 * 64) {
        int k = idx >> 6;
        int n = idx & 63;
        __half h, l;
        split16(W[idx], h, l);
        g_whp[k * 72 + n] = h;
        g_wlp[k * 72 + n] = l;
    }
}

// ---------------- 4. Tensor-core GEMM: xsh = half((x@W) * dinv[row]) ---------
// Split-fp16: x = xh + xl, W = wh + wl; acc = xh*wh + xh*wl + xl*wh in fp32.
// 64-row tile, 128 threads = 4 warps x 16 rows. Whole K=128 in smem.
#define SX_STR 136
#define SW_STR 72
#define SX_HI 0
#define SX_LO 8704
#define SW_HI 17408
#define SW_LO 26624
#define GEMM_SMEM_BYTES ((26624 + 9216) * 2)   // 71680

__device__ __forceinline__ void ldm_x4(unsigned& r0, unsigned& r1,
                                       unsigned& r2, unsigned& r3, unsigned a) {
    asm volatile("ldmatrix.sync.aligned.m8n8.x4.shared.b16 {%0,%1,%2,%3},[%4];"
                 : "=r"(r0), "=r"(r1), "=r"(r2), "=r"(r3) : "r"(a));
}
__device__ __forceinline__ void ldm_x4t(unsigned& r0, unsigned& r1,
                                        unsigned& r2, unsigned& r3, unsigned a) {
    asm volatile("ldmatrix.sync.aligned.m8n8.x4.trans.shared.b16 {%0,%1,%2,%3},[%4];"
                 : "=r"(r0), "=r"(r1), "=r"(r2), "=r"(r3) : "r"(a));
}
__device__ __forceinline__ void mma16816(float* c, const unsigned* a,
                                         const unsigned* b) {
    asm volatile("mma.sync.aligned.m16n8k16.row.col.f32.f16.f16.f32 "
                 "{%0,%1,%2,%3},{%4,%5,%6,%7},{%8,%9},{%0,%1,%2,%3};"
                 : "+f"(c[0]), "+f"(c[1]), "+f"(c[2]), "+f"(c[3])
                 : "r"(a[0]), "r"(a[1]), "r"(a[2]), "r"(a[3]),
                   "r"(b[0]), "r"(b[1]));
}

__global__ void __launch_bounds__(128, 3) k_gemm(const float* __restrict__ x) {
    extern __shared__ __half sh[];
    const int tid = threadIdx.x;
    const int lane = tid & 31;
    const int warp = tid >> 5;
    const int base = blockIdx.x * 64;

    // ---- stage pre-split W: pure uint4 copy (1152 uint4 per buffer) ----
    {
        const uint4* wh4 = (const uint4*)g_whp;
        const uint4* wl4 = (const uint4*)g_wlp;
        uint4* dh = (uint4*)&sh[SW_HI];
        uint4* dl = (uint4*)&sh[SW_LO];
        #pragma unroll
        for (int t = 0; t < 9; t++) {
            int idx = tid + t * 128;          // 0..1151
            dh[idx] = wh4[idx];
            dl[idx] = wl4[idx];
        }
    }
    // ---- stage x tile (64x128) hi/lo with on-the-fly split ----
    {
        const float4* x4 = (const float4*)x;
        #pragma unroll
        for (int t = 0; t < 16; t++) {
            int idx = tid + t * 128;          // 0..2047
            int r = idx >> 5;                 // row in tile (0..63)
            int q = idx & 31;                 // float4 within row
            int row = base + r;
            float4 v = make_float4(0.f, 0.f, 0.f, 0.f);
            if (row < N_NODES) v = x4[row * 32 + q];
            __half h0, l0, h1, l1, h2, l2, h3, l3;
            split16(v.x, h0, l0); split16(v.y, h1, l1);
            split16(v.z, h2, l2); split16(v.w, h3, l3);
            __half2* dh = (__half2*)&sh[SX_HI + r * SX_STR + q * 4];
            __half2* dl = (__half2*)&sh[SX_LO + r * SX_STR + q * 4];
            dh[0] = __halves2half2(h0, h1); dh[1] = __halves2half2(h2, h3);
            dl[0] = __halves2half2(l0, l1); dl[1] = __halves2half2(l2, l3);
        }
    }
    __syncthreads();

    // ---- MMA mainloop ----
    float c[8][4];
    #pragma unroll
    for (int j = 0; j < 8; j++)
        #pragma unroll
        for (int p = 0; p < 4; p++) c[j][p] = 0.f;

    const unsigned sbase = (unsigned)__cvta_generic_to_shared(sh);
    const int quad = lane >> 3;
    const int r8 = lane & 7;
    const int arow = warp * 16 + (quad & 1) * 8 + r8;
    const int acol = (quad >> 1) * 8;
    const int bkr = (quad & 1) * 8 + r8;
    const int bnc = quad >> 1;

    #pragma unroll
    for (int kc = 0; kc < 8; kc++) {
        unsigned ah[4], al[4];
        unsigned aoff = (arow * SX_STR + kc * 16 + acol) * 2;
        ldm_x4(ah[0], ah[1], ah[2], ah[3], sbase + SX_HI * 2 + aoff);
        ldm_x4(al[0], al[1], al[2], al[3], sbase + SX_LO * 2 + aoff);
        #pragma unroll
        for (int j = 0; j < 8; j += 2) {
            unsigned bh[4], bl[4];
            unsigned boff = ((kc * 16 + bkr) * SW_STR + (j + bnc) * 8) * 2;
            ldm_x4t(bh[0], bh[1], bh[2], bh[3], sbase + SW_HI * 2 + boff);
            ldm_x4t(bl[0], bl[1], bl[2], bl[3], sbase + SW_LO * 2 + boff);
            mma16816(c[j], ah, bh);
            mma16816(c[j], ah, bl);
            mma16816(c[j], al, bh);
            mma16816(c[j + 1], ah, bh + 2);
            mma16816(c[j + 1], ah, bl + 2);
            mma16816(c[j + 1], al, bh + 2);
        }
    }

    // ---- epilogue: scale by dinv, fp16 store ----
    const int m0 = base + warp * 16 + (lane >> 2);
    const int m1 = m0 + 8;
    const int n0 = (lane & 3) * 2;
    float d0 = (m0 < N_NODES) ? g_dinv[m0] : 0.f;
    float d1 = (m1 < N_NODES) ? g_dinv[m1] : 0.f;
    #pragma unroll
    for (int j = 0; j < 8; j++) {
        if (m0 < N_NODES)
            *(__half2*)&g_xsh[(size_t)m0 * 64 + j * 8 + n0] =
                __floats2half2_rn(c[j][0] * d0, c[j][1] * d0);
        if (m1 < N_NODES)
            *(__half2*)&g_xsh[(size_t)m1 * 64 + j * 8 + n0] =
                __floats2half2_rn(c[j][2] * d1, c[j][3] * d1);
    }
}

// ---------------- 5. CSR gather-aggregate (fp16 payload) + fused BN stats ----
__global__ void __launch_bounds__(256) k_agg(float* __restrict__ out,
                                             const float* __restrict__ b) {
    __shared__ float s1[COUT], s2m[COUT];
    const int tid = threadIdx.x;
    if (tid < COUT) { s1[tid] = 0.f; s2m[tid] = 0.f; }
    __syncthreads();

    const int gid = blockIdx.x * 256 + tid;
    const int comp = tid & 15;
    float sum0 = 0.f, sum1 = 0.f, sum2 = 0.f, sum3 = 0.f;
    float sq0 = 0.f, sq1 = 0.f, sq2 = 0.f, sq3 = 0.f;

    if (gid < N_NODES * 16) {
        const int node = gid >> 4;
        const uint2* xsh = (const uint2*)g_xsh;   // 16 uint2 per row

        uint2 us = xsh[gid];
        float2 s0 = __half22float2(*(__half2*)&us.x);
        float2 sl1 = __half22float2(*(__half2*)&us.y);
        float4 acc = make_float4(s0.x, s0.y, sl1.x, sl1.y);

        const int beg = g_off[node];
        const int end = beg + g_degi[node];
        int j = beg;
        for (; j + 4 <= end; j += 4) {
            int r0 = g_srow[j], r1 = g_srow[j + 1];
            int r2 = g_srow[j + 2], r3 = g_srow[j + 3];
            uint2 ua = xsh[r0 * 16 + comp];
            uint2 ub = xsh[r1 * 16 + comp];
            uint2 uc = xsh[r2 * 16 + comp];
            uint2 ud = xsh[r3 * 16 + comp];
            float2 a0 = __half22float2(*(__half2*)&ua.x);
            float2 a1 = __half22float2(*(__half2*)&ua.y);
            float2 b0 = __half22float2(*(__half2*)&ub.x);
            float2 b1 = __half22float2(*(__half2*)&ub.y);
            float2 c0 = __half22float2(*(__half2*)&uc.x);
            float2 c1 = __half22float2(*(__half2*)&uc.y);
            float2 d0 = __half22float2(*(__half2*)&ud.x);
            float2 d1 = __half22float2(*(__half2*)&ud.y);
            acc.x += (a0.x + b0.x) + (c0.x + d0.x);
            acc.y += (a0.y + b0.y) + (c0.y + d0.y);
            acc.z += (a1.x + b1.x) + (c1.x + d1.x);
            acc.w += (a1.y + b1.y) + (c1.y + d1.y);
        }
        for (; j < end; j++) {
            uint2 ua = xsh[g_srow[j] * 16 + comp];
            float2 a0 = __half22float2(*(__half2*)&ua.x);
            float2 a1 = __half22float2(*(__half2*)&ua.y);
            acc.x += a0.x; acc.y += a0.y; acc.z += a1.x; acc.w += a1.y;
        }
        const float di = g_dinv[node];
        acc.x *= di; acc.y *= di; acc.z *= di; acc.w *= di;
        ((float4*)out)[gid] = acc;

        const float4 bv = ((const float4*)b)[comp];
        float o0 = acc.x + bv.x, o1 = acc.y + bv.y;
        float o2 = acc.z + bv.z, o3 = acc.w + bv.w;
        sum0 = o0; sq0 = o0 * o0;
        sum1 = o1; sq1 = o1 * o1;
        sum2 = o2; sq2 = o2 * o2;
        sum3 = o3; sq3 = o3 * o3;
    }

    const int cb = comp * 4;
    atomicAdd(&s1[cb + 0], sum0); atomicAdd(&s2m[cb + 0], sq0);
    atomicAdd(&s1[cb + 1], sum1); atomicAdd(&s2m[cb + 1], sq1);
    atomicAdd(&s1[cb + 2], sum2); atomicAdd(&s2m[cb + 2], sq2);
    atomicAdd(&s1[cb + 3], sum3); atomicAdd(&s2m[cb + 3], sq3);
    __syncthreads();
    if (tid < COUT) {
        atomicAdd(&g_sums[tid], s1[tid]);
        atomicAdd(&g_sumsq[tid], s2m[tid]);
    }
}

// ---------------- 6. fold BN + re-zero scratch for next replay ---------------
__global__ void __launch_bounds__(256) k_fold(const float* __restrict__ b,
                                              const float* __restrict__ gamma,
                                              const float* __restrict__ beta) {
    const int bid = blockIdx.x;
    const int tid = threadIdx.x;
    if (bid == 0 && tid < COUT) {
        float inv_n = 1.0f / (float)N_NODES;
        float mean = g_sums[tid] * inv_n;
        float var = g_sumsq[tid] * inv_n - mean * mean;
        float scale = gamma[tid] * rsqrtf(var + 1e-5f);
        g_A[tid] = scale;
        g_B[tid] = scale * (b[tid] - mean) + beta[tid];
        g_sums[tid] = 0.f;
        g_sumsq[tid] = 0.f;
    }
    const int i = bid * 256 + tid;
    if (i < N_NODES) g_degi[i] = 0;
    if (i < 512) { g_flag[i] = 0; g_bsum[i] = 0; }
}

// ---------------- 7. final: y = leaky(A*v + B), in place ----------------
__global__ void __launch_bounds__(256) k_final(float* __restrict__ out) {
    int q = blockIdx.x * 256 + threadIdx.x;
    if (q >= N_NODES * 16) return;
    int cq = q & 15;
    float4 a = ((const float4*)g_A)[cq];
    float4 bb = ((const float4*)g_B)[cq];
    float4 v = ((float4*)out)[q];
    float4 y;
    y.x = a.x * v.x + bb.x;
    y.y = a.y * v.y + bb.y;
    y.z = a.z * v.z + bb.z;
    y.w = a.w * v.w + bb.w;
    y.x = (y.x >= 0.f) ? y.x : 0.01f * y.x;
    y.y = (y.y >= 0.f) ? y.y : 0.01f * y.y;
    y.z = (y.z >= 0.f) ? y.z : 0.01f * y.z;
    y.w = (y.w >= 0.f) ? y.w : 0.01f * y.w;
    ((float4*)out)[q] = y;
}

extern "C" void kernel_launch(void* const* d_in, const int* in_sizes, int n_in,
                              void* d_out, int out_size) {
    const float* x      = (const float*)d_in[0];
    const int*   eidx   = (const int*)d_in[1];     // [2, E]: row then col
    const float* W      = (const float*)d_in[2];
    const float* b      = (const float*)d_in[3];
    const float* gamma  = (const float*)d_in[4];
    const float* beta   = (const float*)d_in[5];
    float* out = (float*)d_out;

    const int* rowIdx = eidx;
    const int* colIdx = eidx + N_EDGES;

    static cudaStream_t s2 = 0;
    static cudaEvent_t evS = 0, evJ = 0;
    static bool init_done = false;
    if (!init_done) {
        cudaFuncSetAttribute(k_gemm, cudaFuncAttributeMaxDynamicSharedMemorySize,
                             GEMM_SMEM_BYTES);
        if (cudaStreamCreateWithFlags(&s2, cudaStreamNonBlocking) != cudaSuccess) s2 = 0;
        if (cudaEventCreateWithFlags(&evS, cudaEventDisableTiming) != cudaSuccess) evS = 0;
        if (cudaEventCreateWithFlags(&evJ, cudaEventDisableTiming) != cudaSuccess) evJ = 0;
        init_done = true;
    }
    const bool fork = (s2 != 0) && (evS != 0) && (evJ != 0);

    if (fork) {
        // s2: wsplit has no dependencies — start immediately
        k_wsplit<<<32, 256, 0, s2>>>(W);
        // main chain
        k_deg<<<(N_EDGES / 4 + 255) / 256, 256>>>(colIdx);
        k_scan1<<<NBLK_SCAN, 256>>>();
        cudaEventRecord(evS, 0);
        // s2: gemm needs dinv (scan) + wsplit; overlaps bin on main
        cudaStreamWaitEvent(s2, evS, 0);
        k_gemm<<<(N_NODES + 63) / 64, 128, GEMM_SMEM_BYTES, s2>>>(x);
        // main: bin overlaps gemm
        k_bin<<<(N_EDGES / 4 + 255) / 256, 256>>>(rowIdx, colIdx);
        cudaEventRecord(evJ, s2);
        cudaStreamWaitEvent(0, evJ, 0);
    } else {
        k_deg<<<(N_EDGES / 4 + 255) / 256, 256>>>(colIdx);
        k_scan1<<<NBLK_SCAN, 256>>>();
        k_wsplit<<<32, 256>>>(W);
        k_bin<<<(N_EDGES / 4 + 255) / 256, 256>>>(rowIdx, colIdx);
        k_gemm<<<(N_NODES + 63) / 64, 128, GEMM_SMEM_BYTES>>>(x);
    }

    k_agg<<<(N_NODES * 16 + 255) / 256, 256>>>(out, b);
    k_fold<<<NBLK_SCAN, 256>>>(b, gamma, beta);
    k_final<<<(N_NODES * 16 + 255) / 256, 256>>>(out);
}

// round 13
// speedup vs baseline: 1.0711x; 1.0711x over previous
#include <cuda_runtime.h>
#include <cuda_fp16.h>

#define N_NODES 100000
#define N_EDGES 1600000
#define COUT 64
#define CIN 128
#define NBLK_SCAN 391   // ceil(100000/256)
#define NBLK_EDGE 1563  // ceil(400000/256)

// ---------------- scratch (no allocations allowed) ----------------
__device__ int    g_degi[N_NODES];               // edge in-degree (no self loop)
__device__ float  g_dinv[N_NODES];
__device__ __half g_xsh[(size_t)N_NODES * COUT]; // (x@W)*dinv[row], fp16 payload
__device__ int    g_off[N_NODES];                // CSR offsets (global)
__device__ int    g_cnt[N_NODES];                // cursor: init=off, bin advances
__device__ int    g_srow[N_EDGES];               // CSR-sorted source row ids
__device__ int    g_bsum[512];
__device__ int    g_flag[512];
__device__ float  g_sums[COUT];
__device__ float  g_sumsq[COUT];
__device__ float  g_A[COUT];
__device__ float  g_B[COUT];
// pre-split W, padded to the smem stride (72 halves/row) for uint4 copy
__device__ __half g_whp[128 * 72];
__device__ __half g_wlp[128 * 72];

__device__ __forceinline__ void split16(float v, __half& h, __half& l) {
    h = __float2half_rn(v);
    l = __float2half_rn(v - __half2float(h));
}

// ---------------- 1. degree count (4 edges/thread) + fused W split -----------
__global__ void k_deg(const int* __restrict__ col, const float* __restrict__ W) {
    const int bid = blockIdx.x;
    if (bid < NBLK_EDGE) {
        int t = bid * 256 + threadIdx.x;
        if (t < N_EDGES / 4) {
            int4 c = ((const int4*)col)[t];
            atomicAdd(&g_degi[c.x], 1);
            atomicAdd(&g_degi[c.y], 1);
            atomicAdd(&g_degi[c.z], 1);
            atomicAdd(&g_degi[c.w], 1);
        }
    } else {
        int idx = (bid - NBLK_EDGE) * 256 + threadIdx.x;   // 0..8191
        if (idx < 128 * 64) {
            int k = idx >> 6;
            int n = idx & 63;
            __half h, l;
            split16(W[idx], h, l);
            g_whp[k * 72 + n] = h;
            g_wlp[k * 72 + n] = l;
        }
    }
}

// ---------------- 2. single-pass scan: dinv + offsets + bin cursor -----------
__global__ void __launch_bounds__(256) k_scan1() {
    __shared__ int s[256];
    __shared__ int r2[256];
    const int tid = threadIdx.x;
    const int bid = blockIdx.x;
    const int i = bid * 256 + tid;
    int v = 0;
    if (i < N_NODES) {
        v = g_degi[i];
        g_dinv[i] = rsqrtf((float)v + 1.0f);   // deg incl self loop
    }
    s[tid] = v;
    __syncthreads();
    #pragma unroll
    for (int d = 1; d < 256; d <<= 1) {
        int t = (tid >= d) ? s[tid - d] : 0;
        __syncthreads();
        s[tid] += t;
        __syncthreads();
    }
    if (tid == 255) {
        atomicExch(&g_bsum[bid], s[255]);
        __threadfence();
        atomicExch(&g_flag[bid], 1);
    }
    int p = 0;
    for (int k = tid; k < bid; k += 256) {
        while (atomicAdd(&g_flag[k], 0) == 0) { }
        p += atomicAdd(&g_bsum[k], 0);
    }
    r2[tid] = p;
    __syncthreads();
    #pragma unroll
    for (int d = 128; d > 0; d >>= 1) {
        if (tid < d) r2[tid] += r2[tid + d];
        __syncthreads();
    }
    if (i < N_NODES) {
        int off = r2[0] + s[tid] - v;
        g_off[i] = off;
        g_cnt[i] = off;          // bin cursor starts at the CSR offset
    }
}

// ---------------- 3. bin: cursor atomic gives absolute position --------------
__global__ void k_bin(const int* __restrict__ rowIdx, const int* __restrict__ colIdx) {
    int t = blockIdx.x * blockDim.x + threadIdx.x;
    if (t < N_EDGES / 4) {
        int4 r = ((const int4*)rowIdx)[t];
        int4 c = ((const int4*)colIdx)[t];
        int p0 = atomicAdd(&g_cnt[c.x], 1);
        int p1 = atomicAdd(&g_cnt[c.y], 1);
        int p2 = atomicAdd(&g_cnt[c.z], 1);
        int p3 = atomicAdd(&g_cnt[c.w], 1);
        g_srow[p0] = r.x;
        g_srow[p1] = r.y;
        g_srow[p2] = r.z;
        g_srow[p3] = r.w;
    }
}

// ---------------- 4. Tensor-core GEMM: xsh = half((x@W) * dinv[row]) ---------
// Split-fp16: x = xh + xl, W = wh + wl; acc = xh*wh + xh*wl + xl*wh in fp32.
#define SX_STR 136
#define SW_STR 72
#define SX_HI 0
#define SX_LO 8704
#define SW_HI 17408
#define SW_LO 26624
#define GEMM_SMEM_BYTES ((26624 + 9216) * 2)   // 71680

__device__ __forceinline__ void ldm_x4(unsigned& r0, unsigned& r1,
                                       unsigned& r2, unsigned& r3, unsigned a) {
    asm volatile("ldmatrix.sync.aligned.m8n8.x4.shared.b16 {%0,%1,%2,%3},[%4];"
                 : "=r"(r0), "=r"(r1), "=r"(r2), "=r"(r3) : "r"(a));
}
__device__ __forceinline__ void ldm_x4t(unsigned& r0, unsigned& r1,
                                        unsigned& r2, unsigned& r3, unsigned a) {
    asm volatile("ldmatrix.sync.aligned.m8n8.x4.trans.shared.b16 {%0,%1,%2,%3},[%4];"
                 : "=r"(r0), "=r"(r1), "=r"(r2), "=r"(r3) : "r"(a));
}
__device__ __forceinline__ void mma16816(float* c, const unsigned* a,
                                         const unsigned* b) {
    asm volatile("mma.sync.aligned.m16n8k16.row.col.f32.f16.f16.f32 "
                 "{%0,%1,%2,%3},{%4,%5,%6,%7},{%8,%9},{%0,%1,%2,%3};"
                 : "+f"(c[0]), "+f"(c[1]), "+f"(c[2]), "+f"(c[3])
                 : "r"(a[0]), "r"(a[1]), "r"(a[2]), "r"(a[3]),
                   "r"(b[0]), "r"(b[1]));
}

__global__ void __launch_bounds__(128, 3) k_gemm(const float* __restrict__ x) {
    extern __shared__ __half sh[];
    const int tid = threadIdx.x;
    const int lane = tid & 31;
    const int warp = tid >> 5;
    const int base = blockIdx.x * 64;

    // ---- stage pre-split W: pure uint4 copy ----
    {
        const uint4* wh4 = (const uint4*)g_whp;
        const uint4* wl4 = (const uint4*)g_wlp;
        uint4* dh = (uint4*)&sh[SW_HI];
        uint4* dl = (uint4*)&sh[SW_LO];
        #pragma unroll
        for (int t = 0; t < 9; t++) {
            int idx = tid + t * 128;          // 0..1151
            dh[idx] = wh4[idx];
            dl[idx] = wl4[idx];
        }
    }
    // ---- stage x tile (64x128) hi/lo with on-the-fly split ----
    {
        const float4* x4 = (const float4*)x;
        #pragma unroll
        for (int t = 0; t < 16; t++) {
            int idx = tid + t * 128;          // 0..2047
            int r = idx >> 5;
            int q = idx & 31;
            int row = base + r;
            float4 v = make_float4(0.f, 0.f, 0.f, 0.f);
            if (row < N_NODES) v = x4[row * 32 + q];
            __half h0, l0, h1, l1, h2, l2, h3, l3;
            split16(v.x, h0, l0); split16(v.y, h1, l1);
            split16(v.z, h2, l2); split16(v.w, h3, l3);
            __half2* dh = (__half2*)&sh[SX_HI + r * SX_STR + q * 4];
            __half2* dl = (__half2*)&sh[SX_LO + r * SX_STR + q * 4];
            dh[0] = __halves2half2(h0, h1); dh[1] = __halves2half2(h2, h3);
            dl[0] = __halves2half2(l0, l1); dl[1] = __halves2half2(l2, l3);
        }
    }
    __syncthreads();

    // ---- MMA mainloop ----
    float c[8][4];
    #pragma unroll
    for (int j = 0; j < 8; j++)
        #pragma unroll
        for (int p = 0; p < 4; p++) c[j][p] = 0.f;

    const unsigned sbase = (unsigned)__cvta_generic_to_shared(sh);
    const int quad = lane >> 3;
    const int r8 = lane & 7;
    const int arow = warp * 16 + (quad & 1) * 8 + r8;
    const int acol = (quad >> 1) * 8;
    const int bkr = (quad & 1) * 8 + r8;
    const int bnc = quad >> 1;

    #pragma unroll
    for (int kc = 0; kc < 8; kc++) {
        unsigned ah[4], al[4];
        unsigned aoff = (arow * SX_STR + kc * 16 + acol) * 2;
        ldm_x4(ah[0], ah[1], ah[2], ah[3], sbase + SX_HI * 2 + aoff);
        ldm_x4(al[0], al[1], al[2], al[3], sbase + SX_LO * 2 + aoff);
        #pragma unroll
        for (int j = 0; j < 8; j += 2) {
            unsigned bh[4], bl[4];
            unsigned boff = ((kc * 16 + bkr) * SW_STR + (j + bnc) * 8) * 2;
            ldm_x4t(bh[0], bh[1], bh[2], bh[3], sbase + SW_HI * 2 + boff);
            ldm_x4t(bl[0], bl[1], bl[2], bl[3], sbase + SW_LO * 2 + boff);
            mma16816(c[j], ah, bh);
            mma16816(c[j], ah, bl);
            mma16816(c[j], al, bh);
            mma16816(c[j + 1], ah, bh + 2);
            mma16816(c[j + 1], ah, bl + 2);
            mma16816(c[j + 1], al, bh + 2);
        }
    }

    // ---- epilogue: scale by dinv, fp16 store ----
    const int m0 = base + warp * 16 + (lane >> 2);
    const int m1 = m0 + 8;
    const int n0 = (lane & 3) * 2;
    float d0 = (m0 < N_NODES) ? g_dinv[m0] : 0.f;
    float d1 = (m1 < N_NODES) ? g_dinv[m1] : 0.f;
    #pragma unroll
    for (int j = 0; j < 8; j++) {
        if (m0 < N_NODES)
            *(__half2*)&g_xsh[(size_t)m0 * 64 + j * 8 + n0] =
                __floats2half2_rn(c[j][0] * d0, c[j][1] * d0);
        if (m1 < N_NODES)
            *(__half2*)&g_xsh[(size_t)m1 * 64 + j * 8 + n0] =
                __floats2half2_rn(c[j][2] * d1, c[j][3] * d1);
    }
}

// ---------------- 5. CSR gather-aggregate (fp16, 8-wide MLP) + BN stats ------
__global__ void __launch_bounds__(256) k_agg(float* __restrict__ out,
                                             const float* __restrict__ b) {
    __shared__ float s1[COUT], s2m[COUT];
    const int tid = threadIdx.x;
    if (tid < COUT) { s1[tid] = 0.f; s2m[tid] = 0.f; }
    __syncthreads();

    const int gid = blockIdx.x * 256 + tid;
    const int comp = tid & 15;
    float sum0 = 0.f, sum1 = 0.f, sum2 = 0.f, sum3 = 0.f;
    float sq0 = 0.f, sq1 = 0.f, sq2 = 0.f, sq3 = 0.f;

    if (gid < N_NODES * 16) {
        const int node = gid >> 4;
        const uint2* xsh = (const uint2*)g_xsh;   // 16 uint2 per row

        uint2 us = xsh[gid];
        float2 sx = __half22float2(*(__half2*)&us.x);
        float2 sy = __half22float2(*(__half2*)&us.y);
        float4 acc = make_float4(sx.x, sx.y, sy.x, sy.y);

        const int beg = g_off[node];
        const int end = beg + g_degi[node];
        int j = beg;
        // 8-wide: batch independent index loads, then 8 independent payloads
        for (; j + 8 <= end; j += 8) {
            int r[8];
            #pragma unroll
            for (int t = 0; t < 8; t++) r[t] = g_srow[j + t];
            uint2 u[8];
            #pragma unroll
            for (int t = 0; t < 8; t++) u[t] = xsh[r[t] * 16 + comp];
            #pragma unroll
            for (int t = 0; t < 8; t++) {
                float2 p0 = __half22float2(*(__half2*)&u[t].x);
                float2 p1 = __half22float2(*(__half2*)&u[t].y);
                acc.x += p0.x; acc.y += p0.y; acc.z += p1.x; acc.w += p1.y;
            }
        }
        for (; j + 4 <= end; j += 4) {
            int r[4];
            #pragma unroll
            for (int t = 0; t < 4; t++) r[t] = g_srow[j + t];
            uint2 u[4];
            #pragma unroll
            for (int t = 0; t < 4; t++) u[t] = xsh[r[t] * 16 + comp];
            #pragma unroll
            for (int t = 0; t < 4; t++) {
                float2 p0 = __half22float2(*(__half2*)&u[t].x);
                float2 p1 = __half22float2(*(__half2*)&u[t].y);
                acc.x += p0.x; acc.y += p0.y; acc.z += p1.x; acc.w += p1.y;
            }
        }
        for (; j < end; j++) {
            uint2 ua = xsh[g_srow[j] * 16 + comp];
            float2 p0 = __half22float2(*(__half2*)&ua.x);
            float2 p1 = __half22float2(*(__half2*)&ua.y);
            acc.x += p0.x; acc.y += p0.y; acc.z += p1.x; acc.w += p1.y;
        }
        const float di = g_dinv[node];
        acc.x *= di; acc.y *= di; acc.z *= di; acc.w *= di;
        ((float4*)out)[gid] = acc;

        const float4 bv = ((const float4*)b)[comp];
        float o0 = acc.x + bv.x, o1 = acc.y + bv.y;
        float o2 = acc.z + bv.z, o3 = acc.w + bv.w;
        sum0 = o0; sq0 = o0 * o0;
        sum1 = o1; sq1 = o1 * o1;
        sum2 = o2; sq2 = o2 * o2;
        sum3 = o3; sq3 = o3 * o3;
    }

    const int cb = comp * 4;
    atomicAdd(&s1[cb + 0], sum0); atomicAdd(&s2m[cb + 0], sq0);
    atomicAdd(&s1[cb + 1], sum1); atomicAdd(&s2m[cb + 1], sq1);
    atomicAdd(&s1[cb + 2], sum2); atomicAdd(&s2m[cb + 2], sq2);
    atomicAdd(&s1[cb + 3], sum3); atomicAdd(&s2m[cb + 3], sq3);
    __syncthreads();
    if (tid < COUT) {
        atomicAdd(&g_sums[tid], s1[tid]);
        atomicAdd(&g_sumsq[tid], s2m[tid]);
    }
}

// ---------------- 6. fold BN + re-zero scratch for next replay ---------------
__global__ void __launch_bounds__(256) k_fold(const float* __restrict__ b,
                                              const float* __restrict__ gamma,
                                              const float* __restrict__ beta) {
    const int bid = blockIdx.x;
    const int tid = threadIdx.x;
    if (bid == 0 && tid < COUT) {
        float inv_n = 1.0f / (float)N_NODES;
        float mean = g_sums[tid] * inv_n;
        float var = g_sumsq[tid] * inv_n - mean * mean;
        float scale = gamma[tid] * rsqrtf(var + 1e-5f);
        g_A[tid] = scale;
        g_B[tid] = scale * (b[tid] - mean) + beta[tid];
        g_sums[tid] = 0.f;
        g_sumsq[tid] = 0.f;
    }
    const int i = bid * 256 + tid;
    if (i < N_NODES) g_degi[i] = 0;
    if (i < 512) { g_flag[i] = 0; g_bsum[i] = 0; }
}

// ---------------- 7. final: y = leaky(A*v + B), in place ----------------
__global__ void __launch_bounds__(256) k_final(float* __restrict__ out) {
    int q = blockIdx.x * 256 + threadIdx.x;
    if (q >= N_NODES * 16) return;
    int cq = q & 15;
    float4 a = ((const float4*)g_A)[cq];
    float4 bb = ((const float4*)g_B)[cq];
    float4 v = ((float4*)out)[q];
    float4 y;
    y.x = a.x * v.x + bb.x;
    y.y = a.y * v.y + bb.y;
    y.z = a.z * v.z + bb.z;
    y.w = a.w * v.w + bb.w;
    y.x = (y.x >= 0.f) ? y.x : 0.01f * y.x;
    y.y = (y.y >= 0.f) ? y.y : 0.01f * y.y;
    y.z = (y.z >= 0.f) ? y.z : 0.01f * y.z;
    y.w = (y.w >= 0.f) ? y.w : 0.01f * y.w;
    ((float4*)out)[q] = y;
}

extern "C" void kernel_launch(void* const* d_in, const int* in_sizes, int n_in,
                              void* d_out, int out_size) {
    const float* x      = (const float*)d_in[0];
    const int*   eidx   = (const int*)d_in[1];     // [2, E]: row then col
    const float* W      = (const float*)d_in[2];
    const float* b      = (const float*)d_in[3];
    const float* gamma  = (const float*)d_in[4];
    const float* beta   = (const float*)d_in[5];
    float* out = (float*)d_out;

    const int* rowIdx = eidx;
    const int* colIdx = eidx + N_EDGES;

    static bool init_done = false;
    if (!init_done) {
        cudaFuncSetAttribute(k_gemm, cudaFuncAttributeMaxDynamicSharedMemorySize,
                             GEMM_SMEM_BYTES);
        init_done = true;
    }

    k_deg<<<NBLK_EDGE + 32, 256>>>(colIdx, W);
    k_scan1<<<NBLK_SCAN, 256>>>();
    k_bin<<<NBLK_EDGE, 256>>>(rowIdx, colIdx);
    k_gemm<<<(N_NODES + 63) / 64, 128, GEMM_SMEM_BYTES>>>(x);
    k_agg<<<(N_NODES * 16 + 255) / 256, 256>>>(out, b);
    k_fold<<<NBLK_SCAN, 256>>>(b, gamma, beta);
    k_final<<<(N_NODES * 16 + 255) / 256, 256>>>(out);
}